// round 14
// baseline (speedup 1.0000x reference)
#include <cuda_runtime.h>
#include <cuda_fp16.h>
#include <cstdint>
#include <math.h>

// ===========================================================================
// Round 14: attention row-sums in f16x2 per-kb (F2F/FADD work /4, ALU-pipe
// HADD2 only); GEMMs with 4-stage cp.async pipeline at occupancy 3.
// ===========================================================================

__device__ __forceinline__ uint32_t smem_u32(const void* p) {
    uint32_t a;
    asm("{ .reg .u64 t; cvta.to.shared.u64 t, %1; cvt.u32.u64 %0, t; }" : "=r"(a) : "l"(p));
    return a;
}
__device__ __forceinline__ void lm4(uint32_t* r, uint32_t a) {
    asm volatile("ldmatrix.sync.aligned.m8n8.x4.shared.b16 {%0,%1,%2,%3}, [%4];"
        : "=r"(r[0]), "=r"(r[1]), "=r"(r[2]), "=r"(r[3]) : "r"(a));
}
__device__ __forceinline__ void lm4t(uint32_t* r, uint32_t a) {
    asm volatile("ldmatrix.sync.aligned.m8n8.x4.trans.shared.b16 {%0,%1,%2,%3}, [%4];"
        : "=r"(r[0]), "=r"(r[1]), "=r"(r[2]), "=r"(r[3]) : "r"(a));
}
__device__ __forceinline__ void mma_f16(float* d, const uint32_t* a, uint32_t b0, uint32_t b1) {
    asm volatile("mma.sync.aligned.m16n8k16.row.col.f32.f16.f16.f32 "
        "{%0,%1,%2,%3}, {%4,%5,%6,%7}, {%8,%9}, {%0,%1,%2,%3};"
        : "+f"(d[0]), "+f"(d[1]), "+f"(d[2]), "+f"(d[3])
        : "r"(a[0]), "r"(a[1]), "r"(a[2]), "r"(a[3]), "r"(b0), "r"(b1));
}
__device__ __forceinline__ void mma_f16h(uint32_t* d, const uint32_t* a, uint32_t b0, uint32_t b1) {
    asm volatile("mma.sync.aligned.m16n8k16.row.col.f16.f16.f16.f16 "
        "{%0,%1}, {%2,%3,%4,%5}, {%6,%7}, {%0,%1};"
        : "+r"(d[0]), "+r"(d[1])
        : "r"(a[0]), "r"(a[1]), "r"(a[2]), "r"(a[3]), "r"(b0), "r"(b1));
}
__device__ __forceinline__ void cpasync16(uint32_t dst, const void* src) {
    asm volatile("cp.async.cg.shared.global [%0], [%1], 16;" :: "r"(dst), "l"(src));
}
__device__ __forceinline__ uint32_t hex2(uint32_t a) {
    uint32_t d; asm("ex2.approx.f16x2 %0, %1;" : "=r"(d) : "r"(a)); return d;
}
__device__ __forceinline__ uint32_t hadd2u(uint32_t a, uint32_t b) {
    uint32_t d; asm("add.rn.f16x2 %0, %1, %2;" : "=r"(d) : "r"(a), "r"(b)); return d;
}

// ---------------- scratch (device globals) ---------------------------------
__device__ __half g_xh[2097152];
__device__ __half g_ws[3145728];
__device__ __half g_wos[1048576];
__device__ __half g_wT[3145728];
__device__ __half g_wc[3145728];
__device__ float g_bc[3072];
__device__ float g_zb[1024];
__device__ __half g_q2f[2097152], g_k2f[2097152], g_v2f[2097152];
__device__ __half g_of[2097152];

// ---------------- fused prep ------------------------------------------------
struct PrepArgs {
    const float* csrc[5];
    __half* cdst[5];
    int cn[5];
    const float* wsrc[3];
    __half* wT;
    const float* V[3];
    const float* bI[3];
    const float* bO[3];
    float* bc;
};

__global__ void __launch_bounds__(256) prep_all(PrepArgs a) {
    const int z = blockIdx.z;
    const int bx = blockIdx.x;
    const int tid = threadIdx.x;
    __shared__ float s[32][33];

    if (z < 5) {
        const int i = (bx * 256 + tid) * 4;
        if (i >= a.cn[z]) return;
        const float4 v = *(const float4*)(a.csrc[z] + i);
        __half2 H0; H0.x = __float2half_rn(v.x); H0.y = __float2half_rn(v.y);
        __half2 H1; H1.x = __float2half_rn(v.z); H1.y = __float2half_rn(v.w);
        *(__half2*)(a.cdst[z] + i) = H0;
        *(__half2*)(a.cdst[z] + i + 2) = H1;
    } else if (z < 8) {
        if (bx >= 1024) return;
        const int zz = z - 5;
        const float* W = a.wsrc[zz];
        __half* ho = a.wT + (size_t)zz * 1048576;
        const int tx = tid & 31;
        const int ty = tid >> 5;
        const int k0 = (bx & 31) * 32;
        const int m0 = (bx >> 5) * 32;
#pragma unroll
        for (int j = 0; j < 4; ++j)
            s[ty + j * 8][tx] = W[(size_t)(m0 + ty + j * 8) * 1024 + k0 + tx];
        __syncthreads();
#pragma unroll
        for (int j = 0; j < 4; ++j)
            ho[(size_t)(k0 + ty + j * 8) * 1024 + m0 + tx] = __float2half_rn(s[tx][ty + j * 8]);
    } else {
        if (bx >= 384) return;
        const int zz = bx >> 7;
        const int lane = tid & 31;
        const int w = tid >> 5;
        const int n = (bx & 127) * 8 + w;
        const float* V = a.V[zz];
        const float* b = a.bI[zz];
        float sum = 0.f;
#pragma unroll
        for (int it = 0; it < 8; ++it) {
            const int k = (it * 32 + lane) * 4;
            const float4 vv = *(const float4*)(V + (size_t)n * 1024 + k);
            const float4 bb = *(const float4*)(b + k);
            sum += vv.x * bb.x + vv.y * bb.y + vv.z * bb.z + vv.w * bb.w;
        }
#pragma unroll
        for (int o = 16; o > 0; o >>= 1) sum += __shfl_xor_sync(0xffffffffu, sum, o);
        if (lane == 0) a.bc[zz * 1024 + n] = sum + a.bO[zz][n];
    }
}

// ---------------- mma.sync GEMM, 1-term fp16, 128x64, 4-stage, occ 3 --------
struct GemmArgs {
    const __half *A, *B;
    const float* bias;
    void* C0;
    int mode;
    float oscale;
};

__device__ __forceinline__ uint32_t swz(int r, int s) {
    return (uint32_t)(r * 64 + ((s ^ ((r >> 1) & 3)) << 4));
}

__global__ void __launch_bounds__(256, 3)
gemm_mma(GemmArgs g0, GemmArgs g1, GemmArgs g2)
{
    constexpr uint32_t SS = 12288u;

    const GemmArgs ga = (blockIdx.z == 0) ? g0 : (blockIdx.z == 1) ? g1 : g2;
    extern __shared__ char smem_raw[];
    const uint32_t sb = (smem_u32(smem_raw) + 1023u) & ~1023u;

    const int tid = threadIdx.x;
    const int lane = tid & 31;
    const int wid = tid >> 5;
    const int wm = wid & 3;
    const int wn = wid >> 2;
    const int bm = blockIdx.y * 128;
    const int bn = blockIdx.x * 64;

    const __half* gp[3];
    uint32_t dst[3];
#pragma unroll
    for (int i = 0; i < 3; ++i) {
        const int u = tid + i * 256;
        if (u < 512) {
            const int r = u >> 2, sc = u & 3;
            gp[i] = ga.A + (size_t)(bm + r) * 1024 + sc * 8;
            dst[i] = sb + swz(r, sc);
        } else {
            const int v = u - 512;
            const int r = v >> 2, sc = v & 3;
            gp[i] = ga.B + (size_t)(bn + r) * 1024 + sc * 8;
            dst[i] = sb + 8192 + swz(r, sc);
        }
    }

    uint32_t lmA[2], lmB[2];
    {
        const int rA = wm * 32 + ((lane >> 3) & 1) * 8 + (lane & 7);
        const int sA = lane >> 4;
#pragma unroll
        for (int mt = 0; mt < 2; ++mt) lmA[mt] = sb + swz(rA + mt * 16, sA);
        const int rB = wn * 32 + (lane >> 4) * 8 + (lane & 7);
        const int sB = (lane >> 3) & 1;
#pragma unroll
        for (int ng = 0; ng < 2; ++ng) lmB[ng] = sb + 8192 + swz(rB + ng * 16, sB);
    }

    float acc[2][2][2][4];
#pragma unroll
    for (int mt = 0; mt < 2; ++mt)
#pragma unroll
        for (int ng = 0; ng < 2; ++ng)
#pragma unroll
            for (int h = 0; h < 2; ++h)
#pragma unroll
                for (int j = 0; j < 4; ++j) acc[mt][ng][h][j] = 0.f;

    // 4-stage prologue: chunks 0..2
#pragma unroll
    for (int p = 0; p < 3; ++p) {
#pragma unroll
        for (int i = 0; i < 3; ++i) cpasync16(dst[i] + (uint32_t)p * SS, gp[i] + p * 32);
        asm volatile("cp.async.commit_group;" ::: "memory");
    }

#pragma unroll 1
    for (int ch = 0; ch < 32; ++ch) {
        if (ch < 30) { asm volatile("cp.async.wait_group 2;" ::: "memory"); }
        else if (ch == 30) { asm volatile("cp.async.wait_group 1;" ::: "memory"); }
        else { asm volatile("cp.async.wait_group 0;" ::: "memory"); }
        __syncthreads();

        if (ch + 3 < 32) {
            const uint32_t sn = (uint32_t)((ch + 3) & 3) * SS;
#pragma unroll
            for (int i = 0; i < 3; ++i) cpasync16(dst[i] + sn, gp[i] + (ch + 3) * 32);
            asm volatile("cp.async.commit_group;" ::: "memory");
        }

        const uint32_t so = (uint32_t)(ch & 3) * SS;
#pragma unroll
        for (int ks = 0; ks < 2; ++ks) {
            const uint32_t kx = (uint32_t)(ks << 5);
            uint32_t ah[2][4], bh[2][4];
#pragma unroll
            for (int mt = 0; mt < 2; ++mt) lm4(ah[mt], (lmA[mt] + so) ^ kx);
#pragma unroll
            for (int ng = 0; ng < 2; ++ng) lm4(bh[ng], (lmB[ng] + so) ^ kx);
#pragma unroll
            for (int ng = 0; ng < 2; ++ng)
#pragma unroll
                for (int mt = 0; mt < 2; ++mt)
#pragma unroll
                    for (int h = 0; h < 2; ++h)
                        mma_f16(acc[mt][ng][h], ah[mt], bh[ng][2 * h], bh[ng][2 * h + 1]);
        }
    }

    const float osc = ga.oscale;
#pragma unroll
    for (int mt = 0; mt < 2; ++mt) {
        const int r0 = bm + wm * 32 + mt * 16 + (lane >> 2);
#pragma unroll
        for (int ng = 0; ng < 2; ++ng)
#pragma unroll
            for (int h = 0; h < 2; ++h) {
                const int col = bn + wn * 32 + ng * 16 + h * 8 + 2 * (lane & 3);
                const float2 b2 = *(const float2*)(ga.bias + col);
                const float* a4 = acc[mt][ng][h];
                const float v00 = (a4[0] + b2.x) * osc, v01 = (a4[1] + b2.y) * osc;
                const float v10 = (a4[2] + b2.x) * osc, v11 = (a4[3] + b2.y) * osc;
                if (ga.mode == 1) {
                    float2 p0; p0.x = v00; p0.y = v01;
                    float2 p1; p1.x = v10; p1.y = v11;
                    *(float2*)((float*)ga.C0 + (size_t)r0 * 1024 + col) = p0;
                    *(float2*)((float*)ga.C0 + (size_t)(r0 + 8) * 1024 + col) = p1;
                } else {
                    __half* hp = (__half*)ga.C0;
                    __half2 H0, H1;
                    H0.x = __float2half_rn(v00); H0.y = __float2half_rn(v01);
                    H1.x = __float2half_rn(v10); H1.y = __float2half_rn(v11);
                    *(__half2*)(hp + (size_t)r0 * 1024 + col) = H0;
                    *(__half2*)(hp + (size_t)(r0 + 8) * 1024 + col) = H1;
                }
            }
    }
}

// ---------------- MMA flash attention ---------------------------------------
// Row sums: HADD2 accumulate in f16x2 across the kb, convert to fp32 once/kb.
#define AK 0u
#define AV 32768u
#define AQ 65536u

__global__ void __launch_bounds__(256, 2)
attention_mma(const __half* __restrict__ q2, const __half* __restrict__ k2,
              const __half* __restrict__ v2, __half* __restrict__ Of)
{
    extern __shared__ char smraw[];
    const uint32_t sb = smem_u32(smraw);

    const int qp = blockIdx.x;
    const int c  = blockIdx.y;
    const int b  = blockIdx.z;
    const int tid = threadIdx.x;
    const int lane = tid & 31;
    const int w = tid >> 5;

#pragma unroll
    for (int i = 0; i < 16; ++i) {
        const int u = tid + i * 256;
        const int arr = u >> 11;
        const int rem = u & 2047;
        const int r = rem >> 1;
        const int half = rem & 1;
        const __half* base = arr ? v2 : k2;
        const __half* src = base + ((size_t)((b << 10) + r) << 10) + (c << 4) + (half << 3);
        const uint32_t dstp = sb + (uint32_t)(arr << 15) + (uint32_t)(r * 32 + ((half ^ ((r >> 2) & 1)) << 4));
        cpasync16(dstp, src);
    }
    asm volatile("cp.async.commit_group;" ::: "memory");

    const uint32_t qoff = (uint32_t)((lane & 15) * 32 + ((((lane >> 4) & 1) ^ ((lane >> 2) & 1)) << 4));
    const uint32_t kloff = (uint32_t)(((lane & 7) + ((lane >> 4) << 3)) * 32 +
                                      ((((lane >> 3) & 1) ^ ((lane >> 2) & 1)) << 4));
    const uint32_t vloff = (uint32_t)(((lane & 7) + (((lane >> 3) & 1) << 3)) * 32 +
                                      ((((lane >> 4) & 1) ^ ((lane >> 2) & 1)) << 4));

    const int ca = c >> 2, e = c & 3;
    const int tt = 2 * e + b;
    const int b2 = tt >> 2, r2 = tt & 3;

#pragma unroll 1
    for (int it = 0; it < 2; ++it) {
        const int qt = qp * 2 + it;
#pragma unroll
        for (int i = 0; i < 2; ++i) {
            const int u = tid + i * 256;
            const int r = u >> 1;
            const int half = u & 1;
            const __half* src = q2 + ((size_t)((b << 10) + (qt << 8) + r) << 10) + (c << 4) + (half << 3);
            const uint32_t dstp = sb + AQ + (uint32_t)(r * 32 + ((half ^ ((r >> 2) & 1)) << 4));
            cpasync16(dstp, src);
        }
        asm volatile("cp.async.commit_group;" ::: "memory");
        asm volatile("cp.async.wait_group 0;" ::: "memory");
        __syncthreads();

        uint32_t qf[2][4];
#pragma unroll
        for (int mt = 0; mt < 2; ++mt)
            lm4(qf[mt], sb + AQ + (uint32_t)((w * 32 + mt * 16) * 32) + qoff);

        float oac[2][2][4];
        float ls[2][2];
#pragma unroll
        for (int mt = 0; mt < 2; ++mt) {
            ls[mt][0] = ls[mt][1] = 0.f;
#pragma unroll
            for (int ht = 0; ht < 2; ++ht)
#pragma unroll
                for (int j = 0; j < 4; ++j) oac[mt][ht][j] = 0.f;
        }

#pragma unroll 1
        for (int kb = 0; kb < 16; ++kb) {
            uint32_t sc16[2][8][2];
#pragma unroll
            for (int mt = 0; mt < 2; ++mt)
#pragma unroll
                for (int j = 0; j < 8; ++j) { sc16[mt][j][0] = 0u; sc16[mt][j][1] = 0u; }

#pragma unroll
            for (int nt = 0; nt < 4; ++nt) {
                const uint32_t s0 = (uint32_t)((kb * 64 + nt * 16) * 32);
                uint32_t kh4[4];
                lm4(kh4, sb + AK + s0 + kloff);
#pragma unroll
                for (int mt = 0; mt < 2; ++mt) {
                    mma_f16h(sc16[mt][2 * nt], qf[mt], kh4[0], kh4[1]);
                    mma_f16h(sc16[mt][2 * nt + 1], qf[mt], kh4[2], kh4[3]);
                }
            }

            // f16x2 partial row sums for this kb: [mt][rr] rr0=row r, rr1=row r+8
            uint32_t lacc[2][2] = {{0u, 0u}, {0u, 0u}};

#pragma unroll
            for (int ks = 0; ks < 4; ++ks) {
                const uint32_t s0 = (uint32_t)((kb * 64 + ks * 16) * 32);
                uint32_t vh4[4];
                lm4t(vh4, sb + AV + s0 + vloff);
#pragma unroll
                for (int mt = 0; mt < 2; ++mt) {
                    uint32_t pa[4];
                    pa[0] = hex2(sc16[mt][2 * ks][0]);
                    pa[1] = hex2(sc16[mt][2 * ks][1]);
                    pa[2] = hex2(sc16[mt][2 * ks + 1][0]);
                    pa[3] = hex2(sc16[mt][2 * ks + 1][1]);
                    mma_f16(oac[mt][0], pa, vh4[0], vh4[1]);
                    mma_f16(oac[mt][1], pa, vh4[2], vh4[3]);
                    lacc[mt][0] = hadd2u(lacc[mt][0], hadd2u(pa[0], pa[2]));
                    lacc[mt][1] = hadd2u(lacc[mt][1], hadd2u(pa[1], pa[3]));
                }
            }
            // convert once per kb
#pragma unroll
            for (int mt = 0; mt < 2; ++mt) {
                const float2 f0 = __half22float2(*(const __half2*)&lacc[mt][0]);
                const float2 f1 = __half22float2(*(const __half2*)&lacc[mt][1]);
                ls[mt][0] += f0.x + f0.y;
                ls[mt][1] += f1.x + f1.y;
            }
        }

#pragma unroll
        for (int mt = 0; mt < 2; ++mt)
#pragma unroll
            for (int rr = 0; rr < 2; ++rr) {
                float s = ls[mt][rr];
                s += __shfl_xor_sync(0xffffffffu, s, 1);
                s += __shfl_xor_sync(0xffffffffu, s, 2);
                ls[mt][rr] = s;
            }

#pragma unroll
        for (int mt = 0; mt < 2; ++mt) {
            const int s_lo = qt * 256 + w * 32 + mt * 16 + (lane >> 2);
            const float inv_lo = 1.0f / ls[mt][0];
            const float inv_hi = 1.0f / ls[mt][1];
#pragma unroll
            for (int ht = 0; ht < 2; ++ht) {
                const int h0 = ht * 8 + 2 * (lane & 3);
#pragma unroll
                for (int rr = 0; rr < 2; ++rr) {
                    const int s = s_lo + rr * 8;
                    const float inv = rr ? inv_hi : inv_lo;
                    const float v0 = oac[mt][ht][rr * 2 + 0] * inv;
                    const float v1 = oac[mt][ht][rr * 2 + 1] * inv;
                    const int s2 = (r2 << 8) | (s >> 2);
                    const int f = (ca << 6) | ((s & 3) << 4) | h0;
                    const size_t off = (((size_t)b2 << 10) + s2) * 1024 + f;
                    __half2 H;
                    H.x = __float2half_rn(v0); H.y = __float2half_rn(v1);
                    *(__half2*)(Of + off) = H;
                }
            }
        }
        __syncthreads();
    }
}

// ---------------------------------------------------------------------------
extern "C" void kernel_launch(void* const* d_in, const int* in_sizes, int n_in,
                              void* d_out, int out_size)
{
    const float* x    = (const float*)d_in[0];
    const float* wq_w = (const float*)d_in[1];
    const float* wq_b = (const float*)d_in[2];
    const float* wk_w = (const float*)d_in[3];
    const float* wk_b = (const float*)d_in[4];
    const float* wv_w = (const float*)d_in[5];
    const float* wv_b = (const float*)d_in[6];
    const float* vq_w = (const float*)d_in[7];
    const float* vq_b = (const float*)d_in[8];
    const float* vk_w = (const float*)d_in[9];
    const float* vk_b = (const float*)d_in[10];
    const float* vv_w = (const float*)d_in[11];
    const float* vv_b = (const float*)d_in[12];
    const float* wo_w = (const float*)d_in[13];
    const float* wo_b = (const float*)d_in[14];
    float* out = (float*)d_out;

    __half *xh, *ws, *wos, *wT, *wc, *q2f, *k2f, *v2f, *of;
    float *bc, *zb;
    cudaGetSymbolAddress((void**)&xh, g_xh);
    cudaGetSymbolAddress((void**)&ws, g_ws);
    cudaGetSymbolAddress((void**)&wos, g_wos);
    cudaGetSymbolAddress((void**)&wT, g_wT);   cudaGetSymbolAddress((void**)&wc, g_wc);
    cudaGetSymbolAddress((void**)&bc, g_bc);   cudaGetSymbolAddress((void**)&zb, g_zb);
    cudaGetSymbolAddress((void**)&q2f, g_q2f); cudaGetSymbolAddress((void**)&k2f, g_k2f);
    cudaGetSymbolAddress((void**)&v2f, g_v2f);
    cudaGetSymbolAddress((void**)&of, g_of);

    // 1) fused prep
    PrepArgs pa;
    pa.csrc[0] = x;    pa.cdst[0] = xh;           pa.cn[0] = 2097152;
    pa.csrc[1] = vq_w; pa.cdst[1] = ws + 0;       pa.cn[1] = 1048576;
    pa.csrc[2] = vk_w; pa.cdst[2] = ws + 1048576; pa.cn[2] = 1048576;
    pa.csrc[3] = vv_w; pa.cdst[3] = ws + 2097152; pa.cn[3] = 1048576;
    pa.csrc[4] = wo_w; pa.cdst[4] = wos;          pa.cn[4] = 1048576;
    pa.wsrc[0] = wq_w; pa.wsrc[1] = wk_w; pa.wsrc[2] = wv_w;
    pa.wT = wT;
    pa.V[0] = vq_w; pa.V[1] = vk_w; pa.V[2] = vv_w;
    pa.bI[0] = wq_b; pa.bI[1] = wk_b; pa.bI[2] = wv_b;
    pa.bO[0] = vq_b; pa.bO[1] = vk_b; pa.bO[2] = vv_b;
    pa.bc = bc;
    prep_all<<<dim3(2048, 1, 9), 256>>>(pa);

    const int gemm_smem = 4 * 12288 + 1024;
    cudaFuncSetAttribute(gemm_mma, cudaFuncAttributeMaxDynamicSharedMemorySize, gemm_smem);

    const float SCL = 0.25f * 1.4426950408889634f;

    // 2) weight combine
    GemmArgs a0{}, a1{}, a2{};
    a0 = {ws + 0, wT + 0, zb, wc + 0, 2, 1.0f};
    a1 = {ws + 1048576, wT + 1048576, zb, wc + 1048576, 2, 1.0f};
    a2 = {ws + 2097152, wT + 2097152, zb, wc + 2097152, 2, 1.0f};
    gemm_mma<<<dim3(16, 8, 3), 256, gemm_smem>>>(a0, a1, a2);

    // 3) data GEMMs
    a0 = {xh, wc + 0, bc + 0, q2f, 2, SCL};
    a1 = {xh, wc + 1048576, bc + 1024, k2f, 2, 1.0f};
    a2 = {xh, wc + 2097152, bc + 2048, v2f, 2, 1.0f};
    gemm_mma<<<dim3(16, 16, 3), 256, gemm_smem>>>(a0, a1, a2);

    // 4) attention
    const int attn_smem = 73728;
    cudaFuncSetAttribute(attention_mma, cudaFuncAttributeMaxDynamicSharedMemorySize, attn_smem);
    attention_mma<<<dim3(2, 64, 2), 256, attn_smem>>>(q2f, k2f, v2f, of);

    // 5) final projection
    a0 = {of, wos, wo_b, out, 1, 1.0f};
    gemm_mma<<<dim3(16, 16, 1), 256, gemm_smem>>>(a0, a0, a0);
}

// round 15
// speedup vs baseline: 1.0143x; 1.0143x over previous
#include <cuda_runtime.h>
#include <cuda_fp16.h>
#include <cstdint>
#include <math.h>

// ===========================================================================
// Round 15: GEMM K-chunk 64 (syncthreads count halved: 16/tile), 128B-row
// swizzle, 3-stage cp.async, occ 2. Attention = R14 config (f16x2 row sums).
// Accumulation order identical to R14 -> same rel_err.
// ===========================================================================

__device__ __forceinline__ uint32_t smem_u32(const void* p) {
    uint32_t a;
    asm("{ .reg .u64 t; cvta.to.shared.u64 t, %1; cvt.u32.u64 %0, t; }" : "=r"(a) : "l"(p));
    return a;
}
__device__ __forceinline__ void lm4(uint32_t* r, uint32_t a) {
    asm volatile("ldmatrix.sync.aligned.m8n8.x4.shared.b16 {%0,%1,%2,%3}, [%4];"
        : "=r"(r[0]), "=r"(r[1]), "=r"(r[2]), "=r"(r[3]) : "r"(a));
}
__device__ __forceinline__ void lm4t(uint32_t* r, uint32_t a) {
    asm volatile("ldmatrix.sync.aligned.m8n8.x4.trans.shared.b16 {%0,%1,%2,%3}, [%4];"
        : "=r"(r[0]), "=r"(r[1]), "=r"(r[2]), "=r"(r[3]) : "r"(a));
}
__device__ __forceinline__ void mma_f16(float* d, const uint32_t* a, uint32_t b0, uint32_t b1) {
    asm volatile("mma.sync.aligned.m16n8k16.row.col.f32.f16.f16.f32 "
        "{%0,%1,%2,%3}, {%4,%5,%6,%7}, {%8,%9}, {%0,%1,%2,%3};"
        : "+f"(d[0]), "+f"(d[1]), "+f"(d[2]), "+f"(d[3])
        : "r"(a[0]), "r"(a[1]), "r"(a[2]), "r"(a[3]), "r"(b0), "r"(b1));
}
__device__ __forceinline__ void mma_f16h(uint32_t* d, const uint32_t* a, uint32_t b0, uint32_t b1) {
    asm volatile("mma.sync.aligned.m16n8k16.row.col.f16.f16.f16.f16 "
        "{%0,%1}, {%2,%3,%4,%5}, {%6,%7}, {%0,%1};"
        : "+r"(d[0]), "+r"(d[1])
        : "r"(a[0]), "r"(a[1]), "r"(a[2]), "r"(a[3]), "r"(b0), "r"(b1));
}
__device__ __forceinline__ void cpasync16(uint32_t dst, const void* src) {
    asm volatile("cp.async.cg.shared.global [%0], [%1], 16;" :: "r"(dst), "l"(src));
}
__device__ __forceinline__ uint32_t hex2(uint32_t a) {
    uint32_t d; asm("ex2.approx.f16x2 %0, %1;" : "=r"(d) : "r"(a)); return d;
}
__device__ __forceinline__ uint32_t hadd2u(uint32_t a, uint32_t b) {
    uint32_t d; asm("add.rn.f16x2 %0, %1, %2;" : "=r"(d) : "r"(a), "r"(b)); return d;
}

// ---------------- scratch (device globals) ---------------------------------
__device__ __half g_xh[2097152];
__device__ __half g_ws[3145728];
__device__ __half g_wos[1048576];
__device__ __half g_wT[3145728];
__device__ __half g_wc[3145728];
__device__ float g_bc[3072];
__device__ float g_zb[1024];
__device__ __half g_q2f[2097152], g_k2f[2097152], g_v2f[2097152];
__device__ __half g_of[2097152];

// ---------------- fused prep ------------------------------------------------
struct PrepArgs {
    const float* csrc[5];
    __half* cdst[5];
    int cn[5];
    const float* wsrc[3];
    __half* wT;
    const float* V[3];
    const float* bI[3];
    const float* bO[3];
    float* bc;
};

__global__ void __launch_bounds__(256) prep_all(PrepArgs a) {
    const int z = blockIdx.z;
    const int bx = blockIdx.x;
    const int tid = threadIdx.x;
    __shared__ float s[32][33];

    if (z < 5) {
        const int i = (bx * 256 + tid) * 4;
        if (i >= a.cn[z]) return;
        const float4 v = *(const float4*)(a.csrc[z] + i);
        __half2 H0; H0.x = __float2half_rn(v.x); H0.y = __float2half_rn(v.y);
        __half2 H1; H1.x = __float2half_rn(v.z); H1.y = __float2half_rn(v.w);
        *(__half2*)(a.cdst[z] + i) = H0;
        *(__half2*)(a.cdst[z] + i + 2) = H1;
    } else if (z < 8) {
        if (bx >= 1024) return;
        const int zz = z - 5;
        const float* W = a.wsrc[zz];
        __half* ho = a.wT + (size_t)zz * 1048576;
        const int tx = tid & 31;
        const int ty = tid >> 5;
        const int k0 = (bx & 31) * 32;
        const int m0 = (bx >> 5) * 32;
#pragma unroll
        for (int j = 0; j < 4; ++j)
            s[ty + j * 8][tx] = W[(size_t)(m0 + ty + j * 8) * 1024 + k0 + tx];
        __syncthreads();
#pragma unroll
        for (int j = 0; j < 4; ++j)
            ho[(size_t)(k0 + ty + j * 8) * 1024 + m0 + tx] = __float2half_rn(s[tx][ty + j * 8]);
    } else {
        if (bx >= 384) return;
        const int zz = bx >> 7;
        const int lane = tid & 31;
        const int w = tid >> 5;
        const int n = (bx & 127) * 8 + w;
        const float* V = a.V[zz];
        const float* b = a.bI[zz];
        float sum = 0.f;
#pragma unroll
        for (int it = 0; it < 8; ++it) {
            const int k = (it * 32 + lane) * 4;
            const float4 vv = *(const float4*)(V + (size_t)n * 1024 + k);
            const float4 bb = *(const float4*)(b + k);
            sum += vv.x * bb.x + vv.y * bb.y + vv.z * bb.z + vv.w * bb.w;
        }
#pragma unroll
        for (int o = 16; o > 0; o >>= 1) sum += __shfl_xor_sync(0xffffffffu, sum, o);
        if (lane == 0) a.bc[zz * 1024 + n] = sum + a.bO[zz][n];
    }
}

// ---------------- mma.sync GEMM, 1-term fp16, 128x64 tile, K-chunk 64 -------
// 128B rows, swizzle: offset = r*128 + ((atom ^ (r&7))<<4). 3 stages, occ 2.
struct GemmArgs {
    const __half *A, *B;
    const float* bias;
    void* C0;
    int mode;
    float oscale;
};

__global__ void __launch_bounds__(256, 2)
gemm_mma(GemmArgs g0, GemmArgs g1, GemmArgs g2)
{
    constexpr uint32_t SS = 24576u;   // stage: A 16KB + B 8KB

    const GemmArgs ga = (blockIdx.z == 0) ? g0 : (blockIdx.z == 1) ? g1 : g2;
    extern __shared__ char smem_raw[];
    const uint32_t sb = (smem_u32(smem_raw) + 1023u) & ~1023u;

    const int tid = threadIdx.x;
    const int lane = tid & 31;
    const int wid = tid >> 5;
    const int wm = wid & 3;
    const int wn = wid >> 2;
    const int bm = blockIdx.y * 128;
    const int bn = blockIdx.x * 64;

    // cp.async: A 1024 atoms + B 512 atoms = 6 per thread
    const __half* gp[6];
    uint32_t dst[6];
#pragma unroll
    for (int i = 0; i < 6; ++i) {
        const int u = tid + i * 256;
        if (u < 1024) {
            const int r = u >> 3, sc = u & 7;
            gp[i] = ga.A + (size_t)(bm + r) * 1024 + sc * 8;
            dst[i] = sb + (uint32_t)(r * 128 + ((sc ^ (r & 7)) << 4));
        } else {
            const int v = u - 1024;
            const int r = v >> 3, sc = v & 7;
            gp[i] = ga.B + (size_t)(bn + r) * 1024 + sc * 8;
            dst[i] = sb + 16384u + (uint32_t)(r * 128 + ((sc ^ (r & 7)) << 4));
        }
    }

    // ldmatrix pre-addresses; per ks XOR with (ks<<5)
    uint32_t lmA[2], lmB[2];
    {
        const int rA = wm * 32 + (lane & 15);           // + mt*16 added below
        const int hA = lane >> 4;
        const int pA = hA ^ (rA & 1);
        const int qA = rA & 6;
#pragma unroll
        for (int mt = 0; mt < 2; ++mt) {
            const int R = rA + mt * 16;
            lmA[mt] = sb + (uint32_t)(R * 128 + (((qA) | (pA ^ 0)) << 4));
            // note: R&7 == rA&7 since mt*16 doesn't change low 3 bits? 16 -> bit4, ok.
        }
        const int rB0 = wn * 32 + ((lane >> 4) << 3) + (lane & 7);
        const int hB = (lane >> 3) & 1;
#pragma unroll
        for (int ng = 0; ng < 2; ++ng) {
            const int R = rB0 + ng * 16;
            const int m = R & 7;
            lmB[ng] = sb + 16384u + (uint32_t)(R * 128 + (((m & 6) | (hB ^ (m & 1))) << 4));
        }
    }

    float acc[2][2][2][4];
#pragma unroll
    for (int mt = 0; mt < 2; ++mt)
#pragma unroll
        for (int ng = 0; ng < 2; ++ng)
#pragma unroll
            for (int h = 0; h < 2; ++h)
#pragma unroll
                for (int j = 0; j < 4; ++j) acc[mt][ng][h][j] = 0.f;

#pragma unroll
    for (int i = 0; i < 6; ++i) cpasync16(dst[i], gp[i]);
    asm volatile("cp.async.commit_group;" ::: "memory");
#pragma unroll
    for (int i = 0; i < 6; ++i) cpasync16(dst[i] + SS, gp[i] + 64);
    asm volatile("cp.async.commit_group;" ::: "memory");

#pragma unroll 1
    for (int ch = 0; ch < 16; ++ch) {
        if (ch < 15) { asm volatile("cp.async.wait_group 1;" ::: "memory"); }
        else         { asm volatile("cp.async.wait_group 0;" ::: "memory"); }
        __syncthreads();

        if (ch + 2 < 16) {
            const uint32_t sn = (uint32_t)((ch + 2) % 3) * SS;
#pragma unroll
            for (int i = 0; i < 6; ++i) cpasync16(dst[i] + sn, gp[i] + (ch + 2) * 64);
            asm volatile("cp.async.commit_group;" ::: "memory");
        }

        const uint32_t so = (uint32_t)(ch % 3) * SS;
#pragma unroll
        for (int ks = 0; ks < 4; ++ks) {
            const uint32_t kx = (uint32_t)(ks << 5);
            uint32_t ah[2][4], bh[2][4];
#pragma unroll
            for (int mt = 0; mt < 2; ++mt) lm4(ah[mt], (lmA[mt] + so) ^ kx);
#pragma unroll
            for (int ng = 0; ng < 2; ++ng) lm4(bh[ng], (lmB[ng] + so) ^ kx);
#pragma unroll
            for (int ng = 0; ng < 2; ++ng)
#pragma unroll
                for (int mt = 0; mt < 2; ++mt)
#pragma unroll
                    for (int h = 0; h < 2; ++h)
                        mma_f16(acc[mt][ng][h], ah[mt], bh[ng][2 * h], bh[ng][2 * h + 1]);
        }
    }

    const float osc = ga.oscale;
#pragma unroll
    for (int mt = 0; mt < 2; ++mt) {
        const int r0 = bm + wm * 32 + mt * 16 + (lane >> 2);
#pragma unroll
        for (int ng = 0; ng < 2; ++ng)
#pragma unroll
            for (int h = 0; h < 2; ++h) {
                const int col = bn + wn * 32 + ng * 16 + h * 8 + 2 * (lane & 3);
                const float2 b2 = *(const float2*)(ga.bias + col);
                const float* a4 = acc[mt][ng][h];
                const float v00 = (a4[0] + b2.x) * osc, v01 = (a4[1] + b2.y) * osc;
                const float v10 = (a4[2] + b2.x) * osc, v11 = (a4[3] + b2.y) * osc;
                if (ga.mode == 1) {
                    float2 p0; p0.x = v00; p0.y = v01;
                    float2 p1; p1.x = v10; p1.y = v11;
                    *(float2*)((float*)ga.C0 + (size_t)r0 * 1024 + col) = p0;
                    *(float2*)((float*)ga.C0 + (size_t)(r0 + 8) * 1024 + col) = p1;
                } else {
                    __half* hp = (__half*)ga.C0;
                    __half2 H0, H1;
                    H0.x = __float2half_rn(v00); H0.y = __float2half_rn(v01);
                    H1.x = __float2half_rn(v10); H1.y = __float2half_rn(v11);
                    *(__half2*)(hp + (size_t)r0 * 1024 + col) = H0;
                    *(__half2*)(hp + (size_t)(r0 + 8) * 1024 + col) = H1;
                }
            }
    }
}

// ---------------- MMA flash attention (R14 config) ---------------------------
#define AK 0u
#define AV 32768u
#define AQ 65536u

__global__ void __launch_bounds__(256, 2)
attention_mma(const __half* __restrict__ q2, const __half* __restrict__ k2,
              const __half* __restrict__ v2, __half* __restrict__ Of)
{
    extern __shared__ char smraw[];
    const uint32_t sb = smem_u32(smraw);

    const int qp = blockIdx.x;
    const int c  = blockIdx.y;
    const int b  = blockIdx.z;
    const int tid = threadIdx.x;
    const int lane = tid & 31;
    const int w = tid >> 5;

#pragma unroll
    for (int i = 0; i < 16; ++i) {
        const int u = tid + i * 256;
        const int arr = u >> 11;
        const int rem = u & 2047;
        const int r = rem >> 1;
        const int half = rem & 1;
        const __half* base = arr ? v2 : k2;
        const __half* src = base + ((size_t)((b << 10) + r) << 10) + (c << 4) + (half << 3);
        const uint32_t dstp = sb + (uint32_t)(arr << 15) + (uint32_t)(r * 32 + ((half ^ ((r >> 2) & 1)) << 4));
        cpasync16(dstp, src);
    }
    asm volatile("cp.async.commit_group;" ::: "memory");

    const uint32_t qoff = (uint32_t)((lane & 15) * 32 + ((((lane >> 4) & 1) ^ ((lane >> 2) & 1)) << 4));
    const uint32_t kloff = (uint32_t)(((lane & 7) + ((lane >> 4) << 3)) * 32 +
                                      ((((lane >> 3) & 1) ^ ((lane >> 2) & 1)) << 4));
    const uint32_t vloff = (uint32_t)(((lane & 7) + (((lane >> 3) & 1) << 3)) * 32 +
                                      ((((lane >> 4) & 1) ^ ((lane >> 2) & 1)) << 4));

    const int ca = c >> 2, e = c & 3;
    const int tt = 2 * e + b;
    const int b2 = tt >> 2, r2 = tt & 3;

#pragma unroll 1
    for (int it = 0; it < 2; ++it) {
        const int qt = qp * 2 + it;
#pragma unroll
        for (int i = 0; i < 2; ++i) {
            const int u = tid + i * 256;
            const int r = u >> 1;
            const int half = u & 1;
            const __half* src = q2 + ((size_t)((b << 10) + (qt << 8) + r) << 10) + (c << 4) + (half << 3);
            const uint32_t dstp = sb + AQ + (uint32_t)(r * 32 + ((half ^ ((r >> 2) & 1)) << 4));
            cpasync16(dstp, src);
        }
        asm volatile("cp.async.commit_group;" ::: "memory");
        asm volatile("cp.async.wait_group 0;" ::: "memory");
        __syncthreads();

        uint32_t qf[2][4];
#pragma unroll
        for (int mt = 0; mt < 2; ++mt)
            lm4(qf[mt], sb + AQ + (uint32_t)((w * 32 + mt * 16) * 32) + qoff);

        float oac[2][2][4];
        float ls[2][2];
#pragma unroll
        for (int mt = 0; mt < 2; ++mt) {
            ls[mt][0] = ls[mt][1] = 0.f;
#pragma unroll
            for (int ht = 0; ht < 2; ++ht)
#pragma unroll
                for (int j = 0; j < 4; ++j) oac[mt][ht][j] = 0.f;
        }

#pragma unroll 1
        for (int kb = 0; kb < 16; ++kb) {
            uint32_t sc16[2][8][2];
#pragma unroll
            for (int mt = 0; mt < 2; ++mt)
#pragma unroll
                for (int j = 0; j < 8; ++j) { sc16[mt][j][0] = 0u; sc16[mt][j][1] = 0u; }

#pragma unroll
            for (int nt = 0; nt < 4; ++nt) {
                const uint32_t s0 = (uint32_t)((kb * 64 + nt * 16) * 32);
                uint32_t kh4[4];
                lm4(kh4, sb + AK + s0 + kloff);
#pragma unroll
                for (int mt = 0; mt < 2; ++mt) {
                    mma_f16h(sc16[mt][2 * nt], qf[mt], kh4[0], kh4[1]);
                    mma_f16h(sc16[mt][2 * nt + 1], qf[mt], kh4[2], kh4[3]);
                }
            }

            uint32_t lacc[2][2] = {{0u, 0u}, {0u, 0u}};

#pragma unroll
            for (int ks = 0; ks < 4; ++ks) {
                const uint32_t s0 = (uint32_t)((kb * 64 + ks * 16) * 32);
                uint32_t vh4[4];
                lm4t(vh4, sb + AV + s0 + vloff);
#pragma unroll
                for (int mt = 0; mt < 2; ++mt) {
                    uint32_t pa[4];
                    pa[0] = hex2(sc16[mt][2 * ks][0]);
                    pa[1] = hex2(sc16[mt][2 * ks][1]);
                    pa[2] = hex2(sc16[mt][2 * ks + 1][0]);
                    pa[3] = hex2(sc16[mt][2 * ks + 1][1]);
                    mma_f16(oac[mt][0], pa, vh4[0], vh4[1]);
                    mma_f16(oac[mt][1], pa, vh4[2], vh4[3]);
                    lacc[mt][0] = hadd2u(lacc[mt][0], hadd2u(pa[0], pa[2]));
                    lacc[mt][1] = hadd2u(lacc[mt][1], hadd2u(pa[1], pa[3]));
                }
            }
#pragma unroll
            for (int mt = 0; mt < 2; ++mt) {
                const float2 f0 = __half22float2(*(const __half2*)&lacc[mt][0]);
                const float2 f1 = __half22float2(*(const __half2*)&lacc[mt][1]);
                ls[mt][0] += f0.x + f0.y;
                ls[mt][1] += f1.x + f1.y;
            }
        }

#pragma unroll
        for (int mt = 0; mt < 2; ++mt)
#pragma unroll
            for (int rr = 0; rr < 2; ++rr) {
                float s = ls[mt][rr];
                s += __shfl_xor_sync(0xffffffffu, s, 1);
                s += __shfl_xor_sync(0xffffffffu, s, 2);
                ls[mt][rr] = s;
            }

#pragma unroll
        for (int mt = 0; mt < 2; ++mt) {
            const int s_lo = qt * 256 + w * 32 + mt * 16 + (lane >> 2);
            const float inv_lo = 1.0f / ls[mt][0];
            const float inv_hi = 1.0f / ls[mt][1];
#pragma unroll
            for (int ht = 0; ht < 2; ++ht) {
                const int h0 = ht * 8 + 2 * (lane & 3);
#pragma unroll
                for (int rr = 0; rr < 2; ++rr) {
                    const int s = s_lo + rr * 8;
                    const float inv = rr ? inv_hi : inv_lo;
                    const float v0 = oac[mt][ht][rr * 2 + 0] * inv;
                    const float v1 = oac[mt][ht][rr * 2 + 1] * inv;
                    const int s2 = (r2 << 8) | (s >> 2);
                    const int f = (ca << 6) | ((s & 3) << 4) | h0;
                    const size_t off = (((size_t)b2 << 10) + s2) * 1024 + f;
                    __half2 H;
                    H.x = __float2half_rn(v0); H.y = __float2half_rn(v1);
                    *(__half2*)(Of + off) = H;
                }
            }
        }
        __syncthreads();
    }
}

// ---------------------------------------------------------------------------
extern "C" void kernel_launch(void* const* d_in, const int* in_sizes, int n_in,
                              void* d_out, int out_size)
{
    const float* x    = (const float*)d_in[0];
    const float* wq_w = (const float*)d_in[1];
    const float* wq_b = (const float*)d_in[2];
    const float* wk_w = (const float*)d_in[3];
    const float* wk_b = (const float*)d_in[4];
    const float* wv_w = (const float*)d_in[5];
    const float* wv_b = (const float*)d_in[6];
    const float* vq_w = (const float*)d_in[7];
    const float* vq_b = (const float*)d_in[8];
    const float* vk_w = (const float*)d_in[9];
    const float* vk_b = (const float*)d_in[10];
    const float* vv_w = (const float*)d_in[11];
    const float* vv_b = (const float*)d_in[12];
    const float* wo_w = (const float*)d_in[13];
    const float* wo_b = (const float*)d_in[14];
    float* out = (float*)d_out;

    __half *xh, *ws, *wos, *wT, *wc, *q2f, *k2f, *v2f, *of;
    float *bc, *zb;
    cudaGetSymbolAddress((void**)&xh, g_xh);
    cudaGetSymbolAddress((void**)&ws, g_ws);
    cudaGetSymbolAddress((void**)&wos, g_wos);
    cudaGetSymbolAddress((void**)&wT, g_wT);   cudaGetSymbolAddress((void**)&wc, g_wc);
    cudaGetSymbolAddress((void**)&bc, g_bc);   cudaGetSymbolAddress((void**)&zb, g_zb);
    cudaGetSymbolAddress((void**)&q2f, g_q2f); cudaGetSymbolAddress((void**)&k2f, g_k2f);
    cudaGetSymbolAddress((void**)&v2f, g_v2f);
    cudaGetSymbolAddress((void**)&of, g_of);

    // 1) fused prep
    PrepArgs pa;
    pa.csrc[0] = x;    pa.cdst[0] = xh;           pa.cn[0] = 2097152;
    pa.csrc[1] = vq_w; pa.cdst[1] = ws + 0;       pa.cn[1] = 1048576;
    pa.csrc[2] = vk_w; pa.cdst[2] = ws + 1048576; pa.cn[2] = 1048576;
    pa.csrc[3] = vv_w; pa.cdst[3] = ws + 2097152; pa.cn[3] = 1048576;
    pa.csrc[4] = wo_w; pa.cdst[4] = wos;          pa.cn[4] = 1048576;
    pa.wsrc[0] = wq_w; pa.wsrc[1] = wk_w; pa.wsrc[2] = wv_w;
    pa.wT = wT;
    pa.V[0] = vq_w; pa.V[1] = vk_w; pa.V[2] = vv_w;
    pa.bI[0] = wq_b; pa.bI[1] = wk_b; pa.bI[2] = wv_b;
    pa.bO[0] = vq_b; pa.bO[1] = vk_b; pa.bO[2] = vv_b;
    pa.bc = bc;
    prep_all<<<dim3(2048, 1, 9), 256>>>(pa);

    const int gemm_smem = 3 * 24576 + 1024;
    cudaFuncSetAttribute(gemm_mma, cudaFuncAttributeMaxDynamicSharedMemorySize, gemm_smem);

    const float SCL = 0.25f * 1.4426950408889634f;

    // 2) weight combine
    GemmArgs a0{}, a1{}, a2{};
    a0 = {ws + 0, wT + 0, zb, wc + 0, 2, 1.0f};
    a1 = {ws + 1048576, wT + 1048576, zb, wc + 1048576, 2, 1.0f};
    a2 = {ws + 2097152, wT + 2097152, zb, wc + 2097152, 2, 1.0f};
    gemm_mma<<<dim3(16, 8, 3), 256, gemm_smem>>>(a0, a1, a2);

    // 3) data GEMMs
    a0 = {xh, wc + 0, bc + 0, q2f, 2, SCL};
    a1 = {xh, wc + 1048576, bc + 1024, k2f, 2, 1.0f};
    a2 = {xh, wc + 2097152, bc + 2048, v2f, 2, 1.0f};
    gemm_mma<<<dim3(16, 16, 3), 256, gemm_smem>>>(a0, a1, a2);

    // 4) attention
    const int attn_smem = 73728;
    cudaFuncSetAttribute(attention_mma, cudaFuncAttributeMaxDynamicSharedMemorySize, attn_smem);
    attention_mma<<<dim3(2, 64, 2), 256, attn_smem>>>(q2f, k2f, v2f, of);

    // 5) final projection
    a0 = {of, wos, wo_b, out, 1, 1.0f};
    gemm_mma<<<dim3(16, 16, 1), 256, gemm_smem>>>(a0, a0, a0);
}